// round 16
// baseline (speedup 1.0000x reference)
#include <cuda_runtime.h>
#include <cuda_fp16.h>
#include <cstdint>

#define NNODES 50000
#define NEDGES 600000
#define GEMM_GRID 296          // 2 CTAs/SM x 148 SMs — perfect packing
#define NTILE_M 391            // ceil(50000/128)
#define NTILES (NTILE_M * 2)   // 782 (n in {0,1})

// ---------------- device scratch (no allocations allowed) ----------------
__device__ int   g_deg[NNODES];
__device__ int   g_off[NNODES + 1];
__device__ int   g_cur[NNODES];
__device__ int   g_srcsorted[NEDGES];

// fp16 planes (stored as ushort bits)
__device__ unsigned short g_xs  [NNODES * 256];   // x hi plane in [0,128) of each 256-row
__device__ unsigned short g_aggs[NNODES * 512];   // agg hi plane
__device__ unsigned short g_hsa [NNODES * 512];   // h0 hi plane
__device__ unsigned short g_hsb [NNODES * 512];   // h1 hi plane

// weight hi planes: [K, 256] row-major
__device__ unsigned short g_Wl0s[256 * 256];
__device__ unsigned short g_Wr0s[256 * 256];
__device__ unsigned short g_Wl1s[512 * 256];
__device__ unsigned short g_Wr1s[512 * 256];
__device__ unsigned short g_Wl2s[512 * 256];
__device__ unsigned short g_Wr2s[512 * 256];

// ---------------- helpers ----------------
__device__ __forceinline__ unsigned short hfbits(float f) {
    __half h = __float2half_rn(f);
    return reinterpret_cast<unsigned short&>(h);
}
__device__ __forceinline__ uint32_t smem_u32(const void* p) {
    return (uint32_t)__cvta_generic_to_shared(p);
}
__device__ __forceinline__ void cp16(uint32_t dst, const void* src, int sz) {
    asm volatile("cp.async.cg.shared.global [%0], [%1], 16, %2;\n"
                 :: "r"(dst), "l"(src), "r"(sz));
}
__device__ __forceinline__ void cp_commit() {
    asm volatile("cp.async.commit_group;\n" ::: "memory");
}

#define LDSM4(R0, R1, R2, R3, ADDR) \
    asm volatile("ldmatrix.sync.aligned.m8n8.x4.shared.b16 {%0,%1,%2,%3}, [%4];" \
                 : "=r"(R0), "=r"(R1), "=r"(R2), "=r"(R3) : "r"(ADDR))
#define LDSM4T(R0, R1, R2, R3, ADDR) \
    asm volatile("ldmatrix.sync.aligned.m8n8.x4.trans.shared.b16 {%0,%1,%2,%3}, [%4];" \
                 : "=r"(R0), "=r"(R1), "=r"(R2), "=r"(R3) : "r"(ADDR))
#define MMA16816(D, A, B) \
    asm volatile("mma.sync.aligned.m16n8k16.row.col.f32.f16.f16.f32 " \
                 "{%0,%1,%2,%3},{%4,%5,%6,%7},{%8,%9},{%0,%1,%2,%3};" \
                 : "+f"((D)[0]), "+f"((D)[1]), "+f"((D)[2]), "+f"((D)[3]) \
                 : "r"((A)[0]), "r"((A)[1]), "r"((A)[2]), "r"((A)[3]), \
                   "r"((B)[0]), "r"((B)[1]))

// ---------------- CSR build ----------------
__global__ void zero_deg_kernel() {
    int i = blockIdx.x * blockDim.x + threadIdx.x;
    if (i < NNODES) g_deg[i] = 0;
}
__global__ void hist_kernel(const int* __restrict__ dst) {
    int e = blockIdx.x * blockDim.x + threadIdx.x;
    if (e < NEDGES) atomicAdd(&g_deg[dst[e]], 1);
}
__global__ void scan_kernel() {
    __shared__ int sums[1024];
    int t = threadIdx.x;
    const int n = NNODES;
    const int chunk = (n + 1023) / 1024;
    int begin = t * chunk;
    int end = begin + chunk; if (end > n) end = n;
    int s = 0;
    for (int i = begin; i < end; ++i) s += g_deg[i];
    sums[t] = s;
    __syncthreads();
    for (int ofs = 1; ofs < 1024; ofs <<= 1) {
        int v = (t >= ofs) ? sums[t - ofs] : 0;
        __syncthreads();
        sums[t] += v;
        __syncthreads();
    }
    int prefix = (t == 0) ? 0 : sums[t - 1];
    for (int i = begin; i < end; ++i) {
        g_off[i] = prefix;
        g_cur[i] = prefix;
        prefix += g_deg[i];
    }
    if (t == 1023) g_off[n] = NEDGES;
}
__global__ void fill_kernel(const int* __restrict__ src, const int* __restrict__ dst) {
    int e = blockIdx.x * blockDim.x + threadIdx.x;
    if (e < NEDGES) {
        int d = dst[e];
        int p = atomicAdd(&g_cur[d], 1);
        g_srcsorted[p] = src[e];
    }
}

// ---------------- merged conversion kernel (x + all 6 weights, hi planes) ----------------
#define NX (NNODES * 128)
__global__ void conv_all_kernel(const float* __restrict__ x,
                                const float* __restrict__ Wl0, const float* __restrict__ Wr0,
                                const float* __restrict__ Wl1, const float* __restrict__ Wr1,
                                const float* __restrict__ Wl2, const float* __restrict__ Wr2,
                                unsigned short* __restrict__ xo,
                                unsigned short* __restrict__ wl0o, unsigned short* __restrict__ wr0o,
                                unsigned short* __restrict__ wl1o, unsigned short* __restrict__ wr1o,
                                unsigned short* __restrict__ wl2o, unsigned short* __restrict__ wr2o) {
    int i = blockIdx.x * blockDim.x + threadIdx.x;
    if (i < NX) {
        int r = i >> 7, c = i & 127;
        xo[r * 256 + c] = hfbits(x[i]);
        return;
    }
    int j = i - NX;
    if (j < 32768)      { wl0o[j] = hfbits(Wl0[j]); return; }
    j -= 32768;
    if (j < 32768)      { wr0o[j] = hfbits(Wr0[j]); return; }
    j -= 32768;
    if (j < 65536)      { wl1o[j] = hfbits(Wl1[j]); return; }
    j -= 65536;
    if (j < 65536)      { wr1o[j] = hfbits(Wr1[j]); return; }
    j -= 65536;
    if (j < 65536)      { wl2o[j] = hfbits(Wl2[j]); return; }
    j -= 65536;
    if (j < 65536)      { wr2o[j] = hfbits(Wr2[j]); }
}
#define CONV_TOTAL (NX + 2 * 32768 + 4 * 65536)

// ---------------- aggregation (hi-plane gather, hi-only store) ----------------
__device__ __forceinline__ void hi_store4(float4 v, unsigned short* hip) {
    unsigned short h0 = hfbits(v.x), h1 = hfbits(v.y), h2 = hfbits(v.z), h3 = hfbits(v.w);
    uint2 hi = make_uint2((uint32_t)h0 | ((uint32_t)h1 << 16),
                          (uint32_t)h2 | ((uint32_t)h3 << 16));
    *(uint2*)hip = hi;
}

__global__ void agg_hi128_kernel(const unsigned short* __restrict__ hs,
                                 unsigned short* __restrict__ outs) {
    int warp = (blockIdx.x * blockDim.x + threadIdx.x) >> 5;
    if (warp >= NNODES) return;
    int lane = threadIdx.x & 31;
    int s = g_off[warp];
    int e = g_off[warp + 1];
    int cnt = e - s;
    float inv = 1.0f / (float)(cnt > 0 ? cnt : 1);
    int c0 = lane * 4;
    unsigned short* orow = outs + (size_t)warp * 256;

    float4 acc = make_float4(0.f, 0.f, 0.f, 0.f);
    for (int i = s; i < e; ++i) {
        int src = g_srcsorted[i];
        uint2 u = *(const uint2*)&hs[(size_t)src * 256 + c0];
        __half2 p;
        float2 f;
        reinterpret_cast<uint32_t&>(p) = u.x; f = __half22float2(p);
        acc.x += f.x; acc.y += f.y;
        reinterpret_cast<uint32_t&>(p) = u.y; f = __half22float2(p);
        acc.z += f.x; acc.w += f.y;
    }
    acc.x *= inv; acc.y *= inv; acc.z *= inv; acc.w *= inv;
    hi_store4(acc, orow + c0);
}

__global__ void agg_hi256_kernel(const unsigned short* __restrict__ hs,
                                 unsigned short* __restrict__ outs) {
    int warp = (blockIdx.x * blockDim.x + threadIdx.x) >> 5;
    if (warp >= NNODES) return;
    int lane = threadIdx.x & 31;
    int s = g_off[warp];
    int e = g_off[warp + 1];
    int cnt = e - s;
    float inv = 1.0f / (float)(cnt > 0 ? cnt : 1);
    int c0 = lane * 4;
    unsigned short* orow = outs + (size_t)warp * 512;

    float4 a0 = make_float4(0.f, 0.f, 0.f, 0.f);
    float4 a1 = make_float4(0.f, 0.f, 0.f, 0.f);
    for (int i = s; i < e; ++i) {
        int src = g_srcsorted[i];
        const unsigned short* row = hs + (size_t)src * 512;
        uint2 u0 = *(const uint2*)&row[c0];
        uint2 u1 = *(const uint2*)&row[c0 + 128];
        __half2 p;
        float2 f;
        reinterpret_cast<uint32_t&>(p) = u0.x; f = __half22float2(p);
        a0.x += f.x; a0.y += f.y;
        reinterpret_cast<uint32_t&>(p) = u0.y; f = __half22float2(p);
        a0.z += f.x; a0.w += f.y;
        reinterpret_cast<uint32_t&>(p) = u1.x; f = __half22float2(p);
        a1.x += f.x; a1.y += f.y;
        reinterpret_cast<uint32_t&>(p) = u1.y; f = __half22float2(p);
        a1.z += f.x; a1.w += f.y;
    }
    a0.x *= inv; a0.y *= inv; a0.z *= inv; a0.w *= inv;
    a1.x *= inv; a1.y *= inv; a1.z *= inv; a1.w *= inv;
    hi_store4(a0, orow + c0);
    hi_store4(a1, orow + 128 + c0);
}

// ---------------- persistent fp16 MMA GEMM, 3-stage pipeline, 1 sync/chunk ----------------
// C = A0@B0 + A1@B1 + bias (+relu). A planes [M, astride] fp16 (hi in [0,Kp)),
// B [Kp,256] fp16. Tiles: 128x128, NTILES total, grid = GEMM_GRID persistent CTAs.
// Chunk stream per CTA: g = 0..nmt*cpt-1; tile = mytiles[g/cpt]; within tile,
// c = g%cpt: pass = c>=cpp (A0/B0 then A1/B1), kb = (c - pass*cpp)*32.
#define AP 40
#define BP 136
#define STAGE_BYTES (128 * AP * 2 + 32 * BP * 2)   // 18944
#define GEMM_DYN_SMEM (3 * STAGE_BYTES)            // 56832

__global__ void __launch_bounds__(256, 2)
gemm_persist_kernel(const unsigned short* __restrict__ A0,
                    const unsigned short* __restrict__ A1,
                    int Kp, int astride,
                    const unsigned short* __restrict__ B0,
                    const unsigned short* __restrict__ B1,
                    const float* __restrict__ bias,
                    float* __restrict__ Cout,
                    unsigned short* __restrict__ Csplit,
                    int relu) {
    extern __shared__ __align__(16) unsigned short dynsmem[];
    const uint32_t sbase = smem_u32(dynsmem);

    const int tid = threadIdx.x;
    const int warp = tid >> 5;
    const int lane = tid & 31;
    const int warp_m = warp & 3;
    const int warp_n = warp >> 2;

    const int cpp = Kp >> 5;
    const int cpt = 2 * cpp;

    int mytiles[3];
    int nmt = 0;
    for (int t = blockIdx.x; t < NTILES; t += gridDim.x) mytiles[nmt++] = t;
    if (nmt == 0) return;
    const int total = nmt * cpt;

    float acc[2][8][4];
#pragma unroll
    for (int mt = 0; mt < 2; ++mt)
#pragma unroll
        for (int nt = 0; nt < 8; ++nt)
#pragma unroll
            for (int q = 0; q < 4; ++q) acc[mt][nt][q] = 0.f;

    // ---- chunk loader ----
    auto load_tile = [&](int g) {
        int ti = g / cpt;
        int c = g - ti * cpt;
        int t = mytiles[ti];
        int pass = (c >= cpp) ? 1 : 0;
        int kb = (c - pass * cpp) << 5;
        int m0 = (t >> 1) * 128;
        int n0 = (t & 1) * 128;
        const unsigned short* A = pass ? A1 : A0;
        const unsigned short* B = pass ? B1 : B0;
        uint32_t ab = sbase + (uint32_t)(g % 3) * STAGE_BYTES;
        uint32_t bb = ab + 128 * AP * 2;
        // A tile: 128 rows x 32 cols
        {
            int r = tid >> 2;
            int kc = (tid & 3) << 3;
#pragma unroll
            for (int i = 0; i < 2; ++i) {
                int row = r + i * 64;
                int grow = m0 + row;
                int ok = grow < NNODES;
                const unsigned short* src = A + (size_t)(ok ? grow : 0) * astride + kb + kc;
                cp16(ab + (row * AP + kc) * 2, src, ok ? 16 : 0);
            }
        }
        // B tile: 32 rows x 128 cols
        {
            int r = tid >> 4;
            int col = (tid & 15) << 3;
#pragma unroll
            for (int i = 0; i < 2; ++i) {
                int row = r + i * 16;
                const unsigned short* src = B + (size_t)(kb + row) * 256 + n0 + col;
                cp16(bb + (row * BP + col) * 2, src, 16);
            }
        }
        cp_commit();
    };

    load_tile(0);
    load_tile(1);

    for (int g = 0; g < total; ++g) {
        if (g + 1 < total) {
            asm volatile("cp.async.wait_group 1;\n" ::: "memory");
        } else {
            asm volatile("cp.async.wait_group 0;\n" ::: "memory");
        }
        __syncthreads();
        if (g + 2 < total) load_tile(g + 2);

        // ---- compute chunk g ----
        uint32_t ab = sbase + (uint32_t)(g % 3) * STAGE_BYTES;
        uint32_t bb = ab + 128 * AP * 2;
#pragma unroll
        for (int k16 = 0; k16 < 32; k16 += 16) {
            uint32_t a[2][4];
#pragma unroll
            for (int mt = 0; mt < 2; ++mt) {
                int mrow = warp_m * 32 + mt * 16 + (lane & 15);
                int kc = k16 + ((lane >> 4) << 3);
                LDSM4(a[mt][0], a[mt][1], a[mt][2], a[mt][3], ab + (mrow * AP + kc) * 2);
            }
            uint32_t b[8][2];
#pragma unroll
            for (int p = 0; p < 4; ++p) {
                int brow2 = k16 + (lane & 15);
                int bcol = warp_n * 64 + p * 16 + ((lane >> 4) << 3);
                LDSM4T(b[2 * p][0], b[2 * p][1], b[2 * p + 1][0], b[2 * p + 1][1],
                       bb + (brow2 * BP + bcol) * 2);
            }
#pragma unroll
            for (int mt = 0; mt < 2; ++mt)
#pragma unroll
                for (int nt = 0; nt < 8; ++nt)
                    MMA16816(acc[mt][nt], a[mt], b[nt]);
        }

        // ---- tile boundary: epilogue + acc reset ----
        int ti = g / cpt;
        if (g - ti * cpt == cpt - 1) {
            int t = mytiles[ti];
            int m0 = (t >> 1) * 128;
            int n0 = (t & 1) * 128;
            int gg = lane >> 2;
            int tg = lane & 3;
#pragma unroll
            for (int mt = 0; mt < 2; ++mt) {
#pragma unroll
                for (int nt = 0; nt < 8; ++nt) {
                    int col = n0 + warp_n * 64 + nt * 8 + tg * 2;
                    float b0 = bias[col], b1 = bias[col + 1];
                    int r0 = m0 + warp_m * 32 + mt * 16 + gg;
                    int r1 = r0 + 8;
                    float v0 = acc[mt][nt][0] + b0;
                    float v1 = acc[mt][nt][1] + b1;
                    float v2 = acc[mt][nt][2] + b0;
                    float v3 = acc[mt][nt][3] + b1;
                    if (relu) {
                        v0 = v0 > 0.f ? v0 : 0.f;
                        v1 = v1 > 0.f ? v1 : 0.f;
                        v2 = v2 > 0.f ? v2 : 0.f;
                        v3 = v3 > 0.f ? v3 : 0.f;
                    }
                    if (r0 < NNODES) {
                        if (Cout) *(float2*)&Cout[(size_t)r0 * 256 + col] = make_float2(v0, v1);
                        if (Csplit) {
                            unsigned short h0 = hfbits(v0), h1 = hfbits(v1);
                            *(uint32_t*)&Csplit[(size_t)r0 * 512 + col] =
                                (uint32_t)h0 | ((uint32_t)h1 << 16);
                        }
                    }
                    if (r1 < NNODES) {
                        if (Cout) *(float2*)&Cout[(size_t)r1 * 256 + col] = make_float2(v2, v3);
                        if (Csplit) {
                            unsigned short h2 = hfbits(v2), h3 = hfbits(v3);
                            *(uint32_t*)&Csplit[(size_t)r1 * 512 + col] =
                                (uint32_t)h2 | ((uint32_t)h3 << 16);
                        }
                    }
#pragma unroll
                    for (int q = 0; q < 4; ++q) acc[mt][nt][q] = 0.f;
                }
            }
        }
    }
}

// ---------------- launch ----------------
extern "C" void kernel_launch(void* const* d_in, const int* in_sizes, int n_in,
                              void* d_out, int out_size) {
    const float* x   = (const float*)d_in[0];
    const int*   ei  = (const int*)d_in[1];
    const float* Wl0 = (const float*)d_in[2];
    const float* bl0 = (const float*)d_in[3];
    const float* Wr0 = (const float*)d_in[4];
    const float* Wl1 = (const float*)d_in[5];
    const float* bl1 = (const float*)d_in[6];
    const float* Wr1 = (const float*)d_in[7];
    const float* Wl2 = (const float*)d_in[8];
    const float* bl2 = (const float*)d_in[9];
    const float* Wr2 = (const float*)d_in[10];
    float* out = (float*)d_out;

    const int* src = ei;
    const int* dst = ei + NEDGES;

    unsigned short *xsp, *aggsp, *hsap, *hsbp;
    unsigned short *wl0p, *wr0p, *wl1p, *wr1p, *wl2p, *wr2p;
    cudaGetSymbolAddress((void**)&xsp, g_xs);
    cudaGetSymbolAddress((void**)&aggsp, g_aggs);
    cudaGetSymbolAddress((void**)&hsap, g_hsa);
    cudaGetSymbolAddress((void**)&hsbp, g_hsb);
    cudaGetSymbolAddress((void**)&wl0p, g_Wl0s);
    cudaGetSymbolAddress((void**)&wr0p, g_Wr0s);
    cudaGetSymbolAddress((void**)&wl1p, g_Wl1s);
    cudaGetSymbolAddress((void**)&wr1p, g_Wr1s);
    cudaGetSymbolAddress((void**)&wl2p, g_Wl2s);
    cudaGetSymbolAddress((void**)&wr2p, g_Wr2s);

    static bool attr_done = false;
    if (!attr_done) {
        cudaFuncSetAttribute(gemm_persist_kernel,
                             cudaFuncAttributeMaxDynamicSharedMemorySize, GEMM_DYN_SMEM);
        attr_done = true;
    }

    // ---- CSR build ----
    zero_deg_kernel<<<(NNODES + 255) / 256, 256>>>();
    hist_kernel<<<(NEDGES + 255) / 256, 256>>>(dst);
    scan_kernel<<<1, 1024>>>();
    fill_kernel<<<(NEDGES + 255) / 256, 256>>>(src, dst);

    // ---- conversions (single kernel) ----
    conv_all_kernel<<<(CONV_TOTAL + 255) / 256, 256>>>(
        x, Wl0, Wr0, Wl1, Wr1, Wl2, Wr2,
        xsp, wl0p, wr0p, wl1p, wr1p, wl2p, wr2p);

    int agg_blocks = (NNODES * 32 + 255) / 256;

    // ---- layer 0: Kp=128, agg from x hi plane ----
    agg_hi128_kernel<<<agg_blocks, 256>>>(xsp, aggsp);
    gemm_persist_kernel<<<GEMM_GRID, 256, GEMM_DYN_SMEM>>>(
        aggsp, xsp, 128, 256, wl0p, wr0p, bl0, nullptr, hsap, 1);

    // ---- layer 1: Kp=256 ----
    agg_hi256_kernel<<<agg_blocks, 256>>>(hsap, aggsp);
    gemm_persist_kernel<<<GEMM_GRID, 256, GEMM_DYN_SMEM>>>(
        aggsp, hsap, 256, 512, wl1p, wr1p, bl1, nullptr, hsbp, 1);

    // ---- layer 2: Kp=256, fp32 output ----
    agg_hi256_kernel<<<agg_blocks, 256>>>(hsbp, aggsp);
    gemm_persist_kernel<<<GEMM_GRID, 256, GEMM_DYN_SMEM>>>(
        aggsp, hsbp, 256, 512, wl2p, wr2p, bl2, out, nullptr, 0);
}